// round 8
// baseline (speedup 1.0000x reference)
#include <cuda_runtime.h>
#include <math.h>

#define BB 4
#define SS 2048
#define DD 768
#define HH 12
#define DH 64
#define M_TOT (BB*SS)   // 8192

// Scratch for Q, K, V in [B, H, S, DH] layout (allocation-free __device__ globals)
__device__ float g_Q[BB*HH*SS*DH];
__device__ float g_K[BB*HH*SS*DH];
__device__ float g_V[BB*HH*SS*DH];

// ---------------------------------------------------------------------------
// QKV projection: Y = X @ W^T + bias, scattered to [B,H,S,DH].
// X: [M_TOT, D] row-major. W: [D, D] row-major (W[n][k]). bias: [D].
// Block tile 128x64, BK=16, 256 threads, each thread computes 8x4.
// blockIdx.y == head index (BN == DH == 64).
// WHICH: 0 -> g_Q, 1 -> g_K, 2 -> g_V
// ---------------------------------------------------------------------------
template<int WHICH>
__global__ void __launch_bounds__(256) qkv_gemm(const float* __restrict__ X,
                                                const float* __restrict__ W,
                                                const float* __restrict__ bias)
{
    constexpr int BM = 128, BN = 64, BK = 16;
    __shared__ float As[BK][BM + 4];
    __shared__ float Bs[BK][BN + 4];

    float* outp = (WHICH == 0) ? g_Q : (WHICH == 1) ? g_K : g_V;

    const int bx  = blockIdx.x;   // M tile
    const int h   = blockIdx.y;   // head == N tile
    const int tid = threadIdx.x;
    const int tm  = (tid >> 4) * 8;  // 0..120
    const int tn  = (tid & 15) * 4;  // 0..60

    const int m0 = bx * BM;
    const int n0 = h * BN;

    float acc[8][4] = {};

    for (int k0 = 0; k0 < DD; k0 += BK) {
        // A tile: 128x16 = 512 float4, 2 per thread
        #pragma unroll
        for (int r = 0; r < 2; r++) {
            int idx = tid + r * 256;
            int row = idx >> 2;
            int q4  = (idx & 3) * 4;
            float4 v = *reinterpret_cast<const float4*>(&X[(size_t)(m0 + row) * DD + k0 + q4]);
            As[q4 + 0][row] = v.x;
            As[q4 + 1][row] = v.y;
            As[q4 + 2][row] = v.z;
            As[q4 + 3][row] = v.w;
        }
        // B tile: 64x16 = 256 float4, 1 per thread
        {
            int row = tid >> 2;
            int q4  = (tid & 3) * 4;
            float4 v = *reinterpret_cast<const float4*>(&W[(size_t)(n0 + row) * DD + k0 + q4]);
            Bs[q4 + 0][row] = v.x;
            Bs[q4 + 1][row] = v.y;
            Bs[q4 + 2][row] = v.z;
            Bs[q4 + 3][row] = v.w;
        }
        __syncthreads();

        #pragma unroll
        for (int k = 0; k < BK; k++) {
            float4 a01 = *reinterpret_cast<const float4*>(&As[k][tm]);
            float4 a23 = *reinterpret_cast<const float4*>(&As[k][tm + 4]);
            float4 bf  = *reinterpret_cast<const float4*>(&Bs[k][tn]);
            float a[8] = {a01.x, a01.y, a01.z, a01.w, a23.x, a23.y, a23.z, a23.w};
            float bv[4] = {bf.x, bf.y, bf.z, bf.w};
            #pragma unroll
            for (int i = 0; i < 8; i++)
                #pragma unroll
                for (int j = 0; j < 4; j++)
                    acc[i][j] += a[i] * bv[j];
        }
        __syncthreads();
    }

    const float4 bvec = *reinterpret_cast<const float4*>(&bias[n0 + tn]);
    #pragma unroll
    for (int i = 0; i < 8; i++) {
        int m  = m0 + tm + i;
        int bb = m / SS, s = m % SS;
        float4 o;
        o.x = acc[i][0] + bvec.x;
        o.y = acc[i][1] + bvec.y;
        o.z = acc[i][2] + bvec.z;
        o.w = acc[i][3] + bvec.w;
        *reinterpret_cast<float4*>(&outp[(((size_t)bb * HH + h) * SS + s) * DH + tn]) = o;
    }
}

// ---------------------------------------------------------------------------
// Flash attention: one CTA handles 64 q-rows of one (b,h). Online softmax.
// grid: (S/64, B*H), 256 threads (16x16), each thread owns 4 q-rows x 4 cols.
// ---------------------------------------------------------------------------
#define LD 68   // padded row length (float4-aligned: 68*4 = 272 bytes)
#define SMEM_FLOATS (4 * 64 * LD + 64)
#define SMEM_BYTES  (SMEM_FLOATS * 4)

__global__ void __launch_bounds__(256) flash_attn(const float* __restrict__ mask,
                                                  float* __restrict__ out)
{
    extern __shared__ float sm[];
    float* Qs = sm;               // [64][LD]
    float* Ks = Qs + 64 * LD;     // [64][LD]
    float* Vs = Ks + 64 * LD;     // [64][LD]
    float* Ps = Vs + 64 * LD;     // [64][LD]
    float* Ms = Ps + 64 * LD;     // [64]

    const int bh  = blockIdx.y;          // 0..47
    const int b   = bh / HH;
    const int h   = bh % HH;
    const int qt  = blockIdx.x;          // 0..31
    const int tid = threadIdx.x;
    const int ty  = tid >> 4;
    const int tx  = tid & 15;
    const int r0  = ty * 4;
    const int c0  = tx * 4;

    const float* Qg    = g_Q + (size_t)bh * SS * DH + (size_t)qt * 64 * DH;
    const float* Kg    = g_K + (size_t)bh * SS * DH;
    const float* Vg    = g_V + (size_t)bh * SS * DH;
    const float* maskb = mask + (size_t)b * SS;

    // Load Q tile, pre-scaled by 1/sqrt(DH) = 0.125
    #pragma unroll
    for (int r = 0; r < 4; r++) {
        int idx  = tid + r * 256;         // 0..1023
        int row  = idx >> 4;
        int col4 = (idx & 15) * 4;
        float4 v = *reinterpret_cast<const float4*>(&Qg[(size_t)row * DH + col4]);
        float* q = &Qs[row * LD + col4];
        q[0] = v.x * 0.125f; q[1] = v.y * 0.125f; q[2] = v.z * 0.125f; q[3] = v.w * 0.125f;
    }

    float m_i[4], l_i[4], Oacc[4][4];
    #pragma unroll
    for (int i = 0; i < 4; i++) {
        m_i[i] = -INFINITY;
        l_i[i] = 0.0f;
        #pragma unroll
        for (int j = 0; j < 4; j++) Oacc[i][j] = 0.0f;
    }

    for (int kt = 0; kt < SS / 64; kt++) {
        // Load K, V tiles
        #pragma unroll
        for (int r = 0; r < 4; r++) {
            int idx  = tid + r * 256;
            int row  = idx >> 4;
            int col4 = (idx & 15) * 4;
            size_t g = ((size_t)kt * 64 + row) * DH + col4;
            float4 kv = *reinterpret_cast<const float4*>(&Kg[g]);
            float4 vv = *reinterpret_cast<const float4*>(&Vg[g]);
            *reinterpret_cast<float4*>(&Ks[row * LD + col4]) = kv;
            *reinterpret_cast<float4*>(&Vs[row * LD + col4]) = vv;
        }
        if (tid < 64) Ms[tid] = maskb[kt * 64 + tid];
        __syncthreads();

        // Scores: sc[i][j] = (Q_scaled[r0+i] . K[c0+j]) + mask[c0+j]
        float sc[4][4] = {};
        #pragma unroll
        for (int d = 0; d < DH; d += 4) {
            float4 a[4], kk[4];
            #pragma unroll
            for (int i = 0; i < 4; i++) a[i]  = *reinterpret_cast<const float4*>(&Qs[(r0 + i) * LD + d]);
            #pragma unroll
            for (int j = 0; j < 4; j++) kk[j] = *reinterpret_cast<const float4*>(&Ks[(c0 + j) * LD + d]);
            #pragma unroll
            for (int i = 0; i < 4; i++)
                #pragma unroll
                for (int j = 0; j < 4; j++)
                    sc[i][j] += a[i].x * kk[j].x + a[i].y * kk[j].y
                              + a[i].z * kk[j].z + a[i].w * kk[j].w;
        }
        float mk[4];
        #pragma unroll
        for (int j = 0; j < 4; j++) mk[j] = Ms[c0 + j];
        #pragma unroll
        for (int i = 0; i < 4; i++)
            #pragma unroll
            for (int j = 0; j < 4; j++) sc[i][j] += mk[j];

        // Online softmax update
        float mnew[4], lt[4];
        #pragma unroll
        for (int i = 0; i < 4; i++) {
            float mx = fmaxf(fmaxf(sc[i][0], sc[i][1]), fmaxf(sc[i][2], sc[i][3]));
            #pragma unroll
            for (int off = 8; off > 0; off >>= 1)
                mx = fmaxf(mx, __shfl_xor_sync(0xffffffffu, mx, off, 16));
            mnew[i] = fmaxf(m_i[i], mx);
        }
        #pragma unroll
        for (int i = 0; i < 4; i++) {
            float rs = 0.0f;
            #pragma unroll
            for (int j = 0; j < 4; j++) {
                float p = __expf(sc[i][j] - mnew[i]);
                Ps[(r0 + i) * LD + c0 + j] = p;
                rs += p;
            }
            #pragma unroll
            for (int off = 8; off > 0; off >>= 1)
                rs += __shfl_xor_sync(0xffffffffu, rs, off, 16);
            lt[i] = rs;
        }
        #pragma unroll
        for (int i = 0; i < 4; i++) {
            float alpha = __expf(m_i[i] - mnew[i]);
            l_i[i] = l_i[i] * alpha + lt[i];
            m_i[i] = mnew[i];
            #pragma unroll
            for (int j = 0; j < 4; j++) Oacc[i][j] *= alpha;
        }
        __syncthreads();   // Ps visible to row group

        // O += P @ V
        #pragma unroll 8
        for (int k = 0; k < 64; k++) {
            float p0 = Ps[(r0 + 0) * LD + k];
            float p1 = Ps[(r0 + 1) * LD + k];
            float p2 = Ps[(r0 + 2) * LD + k];
            float p3 = Ps[(r0 + 3) * LD + k];
            float4 v = *reinterpret_cast<const float4*>(&Vs[k * LD + c0]);
            Oacc[0][0] += p0 * v.x; Oacc[0][1] += p0 * v.y; Oacc[0][2] += p0 * v.z; Oacc[0][3] += p0 * v.w;
            Oacc[1][0] += p1 * v.x; Oacc[1][1] += p1 * v.y; Oacc[1][2] += p1 * v.z; Oacc[1][3] += p1 * v.w;
            Oacc[2][0] += p2 * v.x; Oacc[2][1] += p2 * v.y; Oacc[2][2] += p2 * v.z; Oacc[2][3] += p2 * v.w;
            Oacc[3][0] += p3 * v.x; Oacc[3][1] += p3 * v.y; Oacc[3][2] += p3 * v.z; Oacc[3][3] += p3 * v.w;
        }
        __syncthreads();   // before K/V/P overwrite next iter
    }

    // Write out: ctx layout [B, S, H*DH]
    #pragma unroll
    for (int i = 0; i < 4; i++) {
        float inv = 1.0f / l_i[i];
        int srow = qt * 64 + r0 + i;
        float4 o;
        o.x = Oacc[i][0] * inv;
        o.y = Oacc[i][1] * inv;
        o.z = Oacc[i][2] * inv;
        o.w = Oacc[i][3] * inv;
        *reinterpret_cast<float4*>(&out[((size_t)b * SS + srow) * DD + h * DH + c0]) = o;
    }
}

// ---------------------------------------------------------------------------
// Launch
// ---------------------------------------------------------------------------
extern "C" void kernel_launch(void* const* d_in, const int* in_sizes, int n_in,
                              void* d_out, int out_size)
{
    const float* hs   = (const float*)d_in[0];
    const float* mask = (const float*)d_in[1];
    const float* Wq   = (const float*)d_in[2];
    const float* bq   = (const float*)d_in[3];
    const float* Wk   = (const float*)d_in[4];
    const float* bk   = (const float*)d_in[5];
    const float* Wv   = (const float*)d_in[6];
    const float* bv   = (const float*)d_in[7];
    float* out = (float*)d_out;

    dim3 ggrid(M_TOT / 128, HH);
    qkv_gemm<0><<<ggrid, 256>>>(hs, Wq, bq);
    qkv_gemm<1><<<ggrid, 256>>>(hs, Wk, bk);
    qkv_gemm<2><<<ggrid, 256>>>(hs, Wv, bv);

    cudaFuncSetAttribute(flash_attn, cudaFuncAttributeMaxDynamicSharedMemorySize, SMEM_BYTES);
    dim3 agrid(SS / 64, BB * HH);
    flash_attn<<<agrid, 256, SMEM_BYTES>>>(mask, out);
}

// round 10
// speedup vs baseline: 1.3033x; 1.3033x over previous
#include <cuda_runtime.h>
#include <math.h>

#define BB 4
#define SS 2048
#define DD 768
#define HH 12
#define DH 64
#define M_TOT (BB*SS)   // 8192

// Scratch for Q, K, V in [B, H, S, DH] layout (allocation-free __device__ globals)
__device__ float g_Q[BB*HH*SS*DH];
__device__ float g_K[BB*HH*SS*DH];
__device__ float g_V[BB*HH*SS*DH];

// ---------------------------------------------------------------------------
// QKV projection: Y = X @ W^T + bias, scattered to [B,H,S,DH].
// (unchanged — already near the fp32 FMA roofline)
// ---------------------------------------------------------------------------
template<int WHICH>
__global__ void __launch_bounds__(256) qkv_gemm(const float* __restrict__ X,
                                                const float* __restrict__ W,
                                                const float* __restrict__ bias)
{
    constexpr int BM = 128, BN = 64, BK = 16;
    __shared__ float As[BK][BM + 4];
    __shared__ float Bs[BK][BN + 4];

    float* outp = (WHICH == 0) ? g_Q : (WHICH == 1) ? g_K : g_V;

    const int bx  = blockIdx.x;
    const int h   = blockIdx.y;
    const int tid = threadIdx.x;
    const int tm  = (tid >> 4) * 8;
    const int tn  = (tid & 15) * 4;

    const int m0 = bx * BM;
    const int n0 = h * BN;

    float acc[8][4] = {};

    for (int k0 = 0; k0 < DD; k0 += BK) {
        #pragma unroll
        for (int r = 0; r < 2; r++) {
            int idx = tid + r * 256;
            int row = idx >> 2;
            int q4  = (idx & 3) * 4;
            float4 v = *reinterpret_cast<const float4*>(&X[(size_t)(m0 + row) * DD + k0 + q4]);
            As[q4 + 0][row] = v.x;
            As[q4 + 1][row] = v.y;
            As[q4 + 2][row] = v.z;
            As[q4 + 3][row] = v.w;
        }
        {
            int row = tid >> 2;
            int q4  = (tid & 3) * 4;
            float4 v = *reinterpret_cast<const float4*>(&W[(size_t)(n0 + row) * DD + k0 + q4]);
            Bs[q4 + 0][row] = v.x;
            Bs[q4 + 1][row] = v.y;
            Bs[q4 + 2][row] = v.z;
            Bs[q4 + 3][row] = v.w;
        }
        __syncthreads();

        #pragma unroll
        for (int k = 0; k < BK; k++) {
            float4 a01 = *reinterpret_cast<const float4*>(&As[k][tm]);
            float4 a23 = *reinterpret_cast<const float4*>(&As[k][tm + 4]);
            float4 bf  = *reinterpret_cast<const float4*>(&Bs[k][tn]);
            float a[8] = {a01.x, a01.y, a01.z, a01.w, a23.x, a23.y, a23.z, a23.w};
            float bv[4] = {bf.x, bf.y, bf.z, bf.w};
            #pragma unroll
            for (int i = 0; i < 8; i++)
                #pragma unroll
                for (int j = 0; j < 4; j++)
                    acc[i][j] += a[i] * bv[j];
        }
        __syncthreads();
    }

    const float4 bvec = *reinterpret_cast<const float4*>(&bias[n0 + tn]);
    #pragma unroll
    for (int i = 0; i < 8; i++) {
        int m  = m0 + tm + i;
        int bb = m / SS, s = m % SS;
        float4 o;
        o.x = acc[i][0] + bvec.x;
        o.y = acc[i][1] + bvec.y;
        o.z = acc[i][2] + bvec.z;
        o.w = acc[i][3] + bvec.w;
        *reinterpret_cast<float4*>(&outp[(((size_t)bb * HH + h) * SS + s) * DH + tn]) = o;
    }
}

// ---------------------------------------------------------------------------
// Flash attention v3: 128 q-rows x 128-key tiles, 512 threads (32x16).
// Per-thread: 4 q-rows x 8 key-cols (cols strided by 16), O tile 4x4.
// P buffer has its own pitch LDP=132 (>= KT=128!) — fixes the v2 overflow.
// 1 CTA/SM (168.5 KB smem), 16 warps. grid: (S/128, B*H) = 768 CTAs.
// ---------------------------------------------------------------------------
#define QT 128
#define KT 128
#define NTHR 512
#define LD  68    // pitch for Q/K/V rows (64 cols + pad), float4-aligned
#define LDP 132   // pitch for P rows (128 cols + pad), float4-aligned
#define SMEM_FLOATS ((QT + KT + KT) * LD + QT * LDP + KT)
#define SMEM_BYTES  (SMEM_FLOATS * 4)

__global__ void __launch_bounds__(NTHR, 1) flash_attn(const float* __restrict__ mask,
                                                      float* __restrict__ out)
{
    extern __shared__ float sm[];
    float* Qs = sm;                // [QT][LD]
    float* Ks = Qs + QT * LD;      // [KT][LD]
    float* Vs = Ks + KT * LD;      // [KT][LD]
    float* Ps = Vs + KT * LD;      // [QT][LDP]
    float* Ms = Ps + QT * LDP;     // [KT]

    const int bh  = blockIdx.y;          // 0..47
    const int b   = bh / HH;
    const int h   = bh % HH;
    const int qt  = blockIdx.x;          // 0..15
    const int tid = threadIdx.x;
    const int ty  = tid >> 4;            // 0..31
    const int tx  = tid & 15;            // 0..15
    const int r0  = ty * 4;              // q-row base (0..124)

    const float* Qg    = g_Q + (size_t)bh * SS * DH + (size_t)qt * QT * DH;
    const float* Kg    = g_K + (size_t)bh * SS * DH;
    const float* Vg    = g_V + (size_t)bh * SS * DH;
    const float* maskb = mask + (size_t)b * SS;

    // Load Q tile (128 x 64), pre-scaled by 1/sqrt(DH) = 0.125
    #pragma unroll
    for (int r = 0; r < 4; r++) {
        int idx  = tid + r * NTHR;       // 0..2047
        int row  = idx >> 4;
        int col4 = (idx & 15) * 4;
        float4 v = *reinterpret_cast<const float4*>(&Qg[(size_t)row * DH + col4]);
        float* q = &Qs[row * LD + col4];
        q[0] = v.x * 0.125f; q[1] = v.y * 0.125f; q[2] = v.z * 0.125f; q[3] = v.w * 0.125f;
    }

    float m_i[4], l_i[4], Oacc[4][4];
    #pragma unroll
    for (int i = 0; i < 4; i++) {
        m_i[i] = -INFINITY;
        l_i[i] = 0.0f;
        #pragma unroll
        for (int j = 0; j < 4; j++) Oacc[i][j] = 0.0f;
    }

    for (int kt = 0; kt < SS / KT; kt++) {
        // Load K, V tiles (128 x 64 each): 2048 float4 per matrix, 4/thread
        #pragma unroll
        for (int r = 0; r < 4; r++) {
            int idx  = tid + r * NTHR;   // 0..2047
            int row  = idx >> 4;
            int col4 = (idx & 15) * 4;
            size_t g = ((size_t)kt * KT + row) * DH + col4;
            float4 kv = *reinterpret_cast<const float4*>(&Kg[g]);
            float4 vv = *reinterpret_cast<const float4*>(&Vg[g]);
            *reinterpret_cast<float4*>(&Ks[row * LD + col4]) = kv;
            *reinterpret_cast<float4*>(&Vs[row * LD + col4]) = vv;
        }
        if (tid < KT) Ms[tid] = maskb[kt * KT + tid];
        __syncthreads();

        // Scores: sc[i][j] = Q_scaled[r0+i] . K[tx + 16j]
        float sc[4][8] = {};
        #pragma unroll 4
        for (int d = 0; d < DH; d += 4) {
            float4 a[4], kk[8];
            #pragma unroll
            for (int i = 0; i < 4; i++)
                a[i] = *reinterpret_cast<const float4*>(&Qs[(r0 + i) * LD + d]);
            #pragma unroll
            for (int j = 0; j < 8; j++)
                kk[j] = *reinterpret_cast<const float4*>(&Ks[(tx + 16 * j) * LD + d]);
            #pragma unroll
            for (int i = 0; i < 4; i++)
                #pragma unroll
                for (int j = 0; j < 8; j++)
                    sc[i][j] += a[i].x * kk[j].x + a[i].y * kk[j].y
                              + a[i].z * kk[j].z + a[i].w * kk[j].w;
        }

        // Add mask
        float mk[8];
        #pragma unroll
        for (int j = 0; j < 8; j++) mk[j] = Ms[tx + 16 * j];
        #pragma unroll
        for (int i = 0; i < 4; i++)
            #pragma unroll
            for (int j = 0; j < 8; j++) sc[i][j] += mk[j];

        // Online softmax update (row reductions across the 16 tx lanes)
        #pragma unroll
        for (int i = 0; i < 4; i++) {
            float mx = sc[i][0];
            #pragma unroll
            for (int j = 1; j < 8; j++) mx = fmaxf(mx, sc[i][j]);
            #pragma unroll
            for (int off = 8; off > 0; off >>= 1)
                mx = fmaxf(mx, __shfl_xor_sync(0xffffffffu, mx, off, 16));
            float mnew  = fmaxf(m_i[i], mx);
            float alpha = __expf(m_i[i] - mnew);
            float rs = 0.0f;
            #pragma unroll
            for (int j = 0; j < 8; j++) {
                float p = __expf(sc[i][j] - mnew);
                Ps[(r0 + i) * LDP + tx + 16 * j] = p;
                rs += p;
            }
            #pragma unroll
            for (int off = 8; off > 0; off >>= 1)
                rs += __shfl_xor_sync(0xffffffffu, rs, off, 16);
            l_i[i] = l_i[i] * alpha + rs;
            m_i[i] = mnew;
            #pragma unroll
            for (int j = 0; j < 4; j++) Oacc[i][j] *= alpha;
        }
        // P rows r0..r0+3 are written & read only within this warp
        __syncwarp();

        // O += P @ V  (per thread: O[4 rows][d-cols 4tx..4tx+3])
        #pragma unroll 2
        for (int k4 = 0; k4 < KT; k4 += 4) {
            float4 p[4], v[4];
            #pragma unroll
            for (int i = 0; i < 4; i++)
                p[i] = *reinterpret_cast<const float4*>(&Ps[(r0 + i) * LDP + k4]);
            #pragma unroll
            for (int kk = 0; kk < 4; kk++)
                v[kk] = *reinterpret_cast<const float4*>(&Vs[(k4 + kk) * LD + 4 * tx]);
            #pragma unroll
            for (int i = 0; i < 4; i++) {
                Oacc[i][0] += p[i].x * v[0].x + p[i].y * v[1].x + p[i].z * v[2].x + p[i].w * v[3].x;
                Oacc[i][1] += p[i].x * v[0].y + p[i].y * v[1].y + p[i].z * v[2].y + p[i].w * v[3].y;
                Oacc[i][2] += p[i].x * v[0].z + p[i].y * v[1].z + p[i].z * v[2].z + p[i].w * v[3].z;
                Oacc[i][3] += p[i].x * v[0].w + p[i].y * v[1].w + p[i].z * v[2].w + p[i].w * v[3].w;
            }
        }
        __syncthreads();   // before K/V/M overwrite next iter
    }

    // Write out: ctx layout [B, S, H*DH]; this thread owns d-cols 4tx..4tx+3
    #pragma unroll
    for (int i = 0; i < 4; i++) {
        float inv  = 1.0f / l_i[i];
        int   srow = qt * QT + r0 + i;
        float4 o;
        o.x = Oacc[i][0] * inv;
        o.y = Oacc[i][1] * inv;
        o.z = Oacc[i][2] * inv;
        o.w = Oacc[i][3] * inv;
        *reinterpret_cast<float4*>(&out[((size_t)b * SS + srow) * DD + h * DH + 4 * tx]) = o;
    }
}

// ---------------------------------------------------------------------------
// Launch
// ---------------------------------------------------------------------------
extern "C" void kernel_launch(void* const* d_in, const int* in_sizes, int n_in,
                              void* d_out, int out_size)
{
    const float* hs   = (const float*)d_in[0];
    const float* mask = (const float*)d_in[1];
    const float* Wq   = (const float*)d_in[2];
    const float* bq   = (const float*)d_in[3];
    const float* Wk   = (const float*)d_in[4];
    const float* bk   = (const float*)d_in[5];
    const float* Wv   = (const float*)d_in[6];
    const float* bv   = (const float*)d_in[7];
    float* out = (float*)d_out;

    dim3 ggrid(M_TOT / 128, HH);
    qkv_gemm<0><<<ggrid, 256>>>(hs, Wq, bq);
    qkv_gemm<1><<<ggrid, 256>>>(hs, Wk, bk);
    qkv_gemm<2><<<ggrid, 256>>>(hs, Wv, bv);

    cudaFuncSetAttribute(flash_attn, cudaFuncAttributeMaxDynamicSharedMemorySize, SMEM_BYTES);
    dim3 agrid(SS / QT, BB * HH);
    flash_attn<<<agrid, NTHR, SMEM_BYTES>>>(mask, out);
}